// round 4
// baseline (speedup 1.0000x reference)
#include <cuda_runtime.h>

// SphereDownGeo: y[c,k] = sum_d M_vals[k,d] * x[c, M_cols[k,d]]
// M_cols[k,d] = clip(4k + off, 0, N-1), off in [-6,10).
//
// Dense-window reformulation: route weights into a per-thread dense 16-vector
// indexed by j = col - (4k-6), provably in [0,16) even under clipping, then
// y[c,k] = sum_j w16[j] * window[c][4t+2+j] -- a contiguous aligned window
// read via 5x conflict-free LDS.128 per channel. No data-dependent SMEM
// gather (R2's L1=69% bank-conflict limiter).

#define KPB   256
#define DEG   16
#define CCH   8
#define SEGV  260               // float4s per channel window (1040 floats)

__global__ __launch_bounds__(KPB)
void sphere_down_kernel(const float*  __restrict__ x,
                        const int*    __restrict__ M_cols,
                        const float*  __restrict__ M_vals,
                        const int*    __restrict__ cell_ids,
                        float*        __restrict__ out,
                        int n_in, int k_out)
{
    __shared__ float4 xs4[CCH][SEGV];

    const int k0 = blockIdx.x * KPB;
    const int t  = threadIdx.x;
    const int k  = k0 + t;

    // Window base in float4 units: base float index = 4*k0 - 8 (16B aligned).
    const int vbase = k0 - 2;
    const int nv    = n_in >> 2;           // N_IN % 4 == 0

    // ---- Stage x window for all channels (LDG.128/STS.128, zero-fill OOB) ----
    const float4* __restrict__ x4 = (const float4*)x;
    for (int j = t; j < CCH * SEGV; j += KPB) {
        int c = j / SEGV;
        int i = j - c * SEGV;
        int v = vbase + i;
        float4 val = make_float4(0.f, 0.f, 0.f, 0.f);
        if ((unsigned)v < (unsigned)nv)
            val = x4[(size_t)c * nv + v];
        xs4[c][i] = val;
    }

    // ---- Load cols/vals (vectorized, coalesced), route into dense w16 ----
    float w16[DEG];
    #pragma unroll
    for (int j = 0; j < DEG; j++) w16[j] = 0.0f;

    {
        const int4*   cp = (const int4*)(M_cols + (size_t)k * DEG);
        const float4* vp = (const float4*)(M_vals + (size_t)k * DEG);
        const int jref = 4 * k - 6;        // j = col - jref in [0,16)
        #pragma unroll
        for (int i = 0; i < 4; i++) {
            int4   c4 = cp[i];
            float4 v4 = vp[i];
            int   jj[4] = { c4.x - jref, c4.y - jref, c4.z - jref, c4.w - jref };
            float vv[4] = { v4.x, v4.y, v4.z, v4.w };
            #pragma unroll
            for (int q = 0; q < 4; q++) {
                #pragma unroll
                for (int s = 0; s < DEG; s++)
                    if (jj[q] == s) w16[s] += vv[q];
            }
        }
    }

    __syncthreads();

    // ---- Per channel: 5x LDS.128 window (floats [4t, 4t+20)), 16 FMAs ----
    #pragma unroll
    for (int c = 0; c < CCH; c++) {
        float4 a  = xs4[c][t + 0];
        float4 b  = xs4[c][t + 1];
        float4 cc = xs4[c][t + 2];
        float4 dd = xs4[c][t + 3];
        float4 e  = xs4[c][t + 4];
        float win[20] = { a.x,a.y,a.z,a.w,  b.x,b.y,b.z,b.w,
                          cc.x,cc.y,cc.z,cc.w, dd.x,dd.y,dd.z,dd.w,
                          e.x,e.y,e.z,e.w };
        float acc = 0.0f;
        #pragma unroll
        for (int j = 0; j < DEG; j++)
            acc = fmaf(w16[j], win[j + 2], acc);
        out[(size_t)c * k_out + k] = acc;
    }

    // ---- cell_ids pass-through (second tuple element) ----
    out[(size_t)CCH * k_out + k] = (float)cell_ids[k];
}

extern "C" void kernel_launch(void* const* d_in, const int* in_sizes, int n_in_args,
                              void* d_out, int out_size)
{
    const float* x        = (const float*)d_in[0];   // (1, 8, N_IN) f32
    const int*   M_cols   = (const int*)  d_in[1];   // (K_OUT, 16) i32
    const float* M_vals   = (const float*)d_in[2];   // (K_OUT, 16) f32
    const int*   cell_ids = (const int*)  d_in[3];   // (K_OUT,)    i32

    const int N_IN  = in_sizes[0] / CCH;      // 3,145,728
    const int K_OUT = in_sizes[3];            // 786,432

    float* out = (float*)d_out;

    const int grid = (K_OUT + KPB - 1) / KPB; // 3072, exact
    sphere_down_kernel<<<grid, KPB>>>(x, M_cols, M_vals, cell_ids, out,
                                      N_IN, K_OUT);
}

// round 5
// speedup vs baseline: 5.6155x; 5.6155x over previous
#include <cuda_runtime.h>

// SphereDownGeo: y[c,k] = sum_d M_vals[k,d] * x[c, M_cols[k,d]]
// M_cols[k,d] = clip(4k + off, 0, N-1), off in [-6,10) -> windowed gather.
//
// R2 structure (SMEM window + gather) with an XOR bank swizzle on the window:
// logical float index f stored at f ^ ((f>>2)&0x18). Breaks the stride-4
// 4-way bank coset degeneracy that made R2 L1-bound (69.4%).

#define KPB   256
#define DEG   16
#define CCH   8
#define SEG   1040              // logical window floats per channel
#define SEGP  1056              // padded to multiple of 32 for swizzle safety
#define SEGV  260               // logical float4s per channel window

__global__ __launch_bounds__(KPB)
void sphere_down_kernel(const float*  __restrict__ x,
                        const int*    __restrict__ M_cols,
                        const float*  __restrict__ M_vals,
                        const int*    __restrict__ cell_ids,
                        float*        __restrict__ out,
                        int n_in, int k_out)
{
    __shared__ float xs[CCH][SEGP];

    const int k0 = blockIdx.x * KPB;
    const int t  = threadIdx.x;
    const int k  = k0 + t;

    // Window base: float index fb = 4*k0 - 8 (16B aligned). All clipped cols
    // satisfy idx = col - fb in [0, 1040): low clip -> idx >= 8 (block 0),
    // high clip -> idx <= 1031 (last block), unclipped -> [2, 1037].
    const int vbase = k0 - 2;              // float4 index into x
    const int nv    = n_in >> 2;           // N_IN % 4 == 0
    const int fb    = 4 * k0 - 8;

    // ---- Stage x window, vectorized + swizzled (conflict-free STS.128) ----
    const float4* __restrict__ x4 = (const float4*)x;
    for (int j = t; j < CCH * SEGV; j += KPB) {
        int c = j / SEGV;
        int i = j - c * SEGV;              // logical float4 index in window
        int v = vbase + i;
        float4 val = make_float4(0.f, 0.f, 0.f, 0.f);
        if ((unsigned)v < (unsigned)nv)
            val = x4[(size_t)c * nv + v];
        int p4 = i ^ ((i >> 2) & 6);       // float4-level swizzle
        ((float4*)xs[c])[p4] = val;
    }

    // ---- Load this thread's cols/vals (vectorized, coalesced), precompute
    //      swizzled SMEM offsets ----
    int   ph[DEG];
    float vals[DEG];
    {
        const int4*   cp = (const int4*)(M_cols + (size_t)k * DEG);
        const float4* vp = (const float4*)(M_vals + (size_t)k * DEG);
        #pragma unroll
        for (int i = 0; i < 4; i++) {
            int4   c4 = cp[i];
            float4 v4 = vp[i];
            int idx0 = c4.x - fb, idx1 = c4.y - fb,
                idx2 = c4.z - fb, idx3 = c4.w - fb;
            ph[4*i + 0] = idx0 ^ ((idx0 >> 2) & 0x18);
            ph[4*i + 1] = idx1 ^ ((idx1 >> 2) & 0x18);
            ph[4*i + 2] = idx2 ^ ((idx2 >> 2) & 0x18);
            ph[4*i + 3] = idx3 ^ ((idx3 >> 2) & 0x18);
            vals[4*i + 0] = v4.x;  vals[4*i + 1] = v4.y;
            vals[4*i + 2] = v4.z;  vals[4*i + 3] = v4.w;
        }
    }

    __syncthreads();

    // ---- Gather-reduce per channel (swizzled, ~conflict-free), store ----
    #pragma unroll
    for (int c = 0; c < CCH; c++) {
        float acc = 0.0f;
        #pragma unroll
        for (int d = 0; d < DEG; d++)
            acc = fmaf(vals[d], xs[c][ph[d]], acc);
        out[(size_t)c * k_out + k] = acc;
    }

    // ---- cell_ids pass-through (second tuple element) ----
    out[(size_t)CCH * k_out + k] = (float)cell_ids[k];
}

extern "C" void kernel_launch(void* const* d_in, const int* in_sizes, int n_in_args,
                              void* d_out, int out_size)
{
    const float* x        = (const float*)d_in[0];   // (1, 8, N_IN) f32
    const int*   M_cols   = (const int*)  d_in[1];   // (K_OUT, 16) i32
    const float* M_vals   = (const float*)d_in[2];   // (K_OUT, 16) f32
    const int*   cell_ids = (const int*)  d_in[3];   // (K_OUT,)    i32

    const int N_IN  = in_sizes[0] / CCH;      // 3,145,728
    const int K_OUT = in_sizes[3];            // 786,432

    float* out = (float*)d_out;

    const int grid = (K_OUT + KPB - 1) / KPB; // 3072, exact
    sphere_down_kernel<<<grid, KPB>>>(x, M_cols, M_vals, cell_ids, out,
                                      N_IN, K_OUT);
}

// round 7
// speedup vs baseline: 6.0969x; 1.0857x over previous
#include <cuda_runtime.h>

// SphereDownGeo: y[c,k] = sum_d M_vals[k,d] * x[c, M_cols[k,d]]
// M_cols[k,d] = clip(4k + off, 0, N-1), off in [-6,10).
//
// Dense-window form: route weights into a dense 16-vector w[j],
// j = col - (4k-6) in [0,16), via a conflict-free SMEM scatter
// (17-float row stride, thread-private rows). Then
//   y[c,k] = sum_j w[j] * window[c][4t+2+j]
// with the window read as 5x conflict-free LDS.128 per channel.
// Replaces the random-conflict scalar gather (E[max bank load]~3.2,
// measured L1=70% limiter in R2/R5).

#define KPB    256
#define DEG    16
#define CCH    8
#define SEGV   260                 // float4s per channel window (1040 floats)
#define WSTR   17                  // scratch row stride (coprime with 32)

__global__ __launch_bounds__(KPB)
void sphere_down_kernel(const float*  __restrict__ x,
                        const int*    __restrict__ M_cols,
                        const float*  __restrict__ M_vals,
                        const int*    __restrict__ cell_ids,
                        float*        __restrict__ out,
                        int n_in, int k_out)
{
    // Union: weight scratch (256*17*4 = 17,408 B) is used BEFORE the
    // window (8*260*16 = 33,280 B) is staged into the same bytes.
    __shared__ __align__(16) unsigned char smem_raw[CCH * SEGV * 16];
    float*  wscr = (float*)smem_raw;
    float4* xs4  = (float4*)smem_raw;

    const int k0 = blockIdx.x * KPB;
    const int t  = threadIdx.x;
    const int k  = k0 + t;

    const int vbase = k0 - 2;          // float4 window base: float idx 4*k0-8
    const int nv    = n_in >> 2;       // N_IN % 4 == 0

    // ---- Phase 1: dense weight routing (thread-private scratch row) ----
    float* wrow = wscr + t * WSTR;
    #pragma unroll
    for (int j = 0; j < DEG; j++) wrow[j] = 0.0f;

    {
        const int4*   cp = (const int4*)(M_cols + (size_t)k * DEG);
        const float4* vp = (const float4*)(M_vals + (size_t)k * DEG);
        const int jref = 4 * k - 6;    // j = col - jref, provably in [0,16)
        #pragma unroll
        for (int i = 0; i < 4; i++) {
            int4   c4 = cp[i];
            float4 v4 = vp[i];
            wrow[c4.x - jref] += v4.x;
            wrow[c4.y - jref] += v4.y;
            wrow[c4.z - jref] += v4.z;
            wrow[c4.w - jref] += v4.w;
        }
    }

    // Read dense weights back to registers.
    float w0 = wrow[0],  w1 = wrow[1],  w2 = wrow[2],  w3 = wrow[3];
    float w4 = wrow[4],  w5 = wrow[5],  w6 = wrow[6],  w7 = wrow[7];
    float w8 = wrow[8],  w9 = wrow[9],  wA = wrow[10], wB = wrow[11];
    float wC = wrow[12], wD = wrow[13], wE = wrow[14], wF = wrow[15];

    __syncthreads();   // scratch reads done before window overwrites it

    // ---- Phase 2: stage x window, vectorized + coalesced, zero-fill OOB ----
    const float4* __restrict__ x4 = (const float4*)x;
    for (int jj = t; jj < CCH * SEGV; jj += KPB) {
        int c = jj / SEGV;
        int i = jj - c * SEGV;
        int v = vbase + i;
        float4 val = make_float4(0.f, 0.f, 0.f, 0.f);
        if ((unsigned)v < (unsigned)nv)
            val = x4[(size_t)c * nv + v];
        xs4[c * SEGV + i] = val;
    }

    __syncthreads();

    // ---- Phase 3: per channel, 5x conflict-free LDS.128 + 16 FMAs ----
    #pragma unroll
    for (int c = 0; c < CCH; c++) {
        const float4* base = xs4 + c * SEGV + t;
        float4 a  = base[0];
        float4 b  = base[1];
        float4 cc = base[2];
        float4 dd = base[3];
        float4 e  = base[4];
        // window float j maps to position 4t+2+j
        float acc0 = w0 * a.z;
        float acc1 = w1 * a.w;
        acc0 = fmaf(w2, b.x,  acc0);  acc1 = fmaf(w3, b.y,  acc1);
        acc0 = fmaf(w4, b.z,  acc0);  acc1 = fmaf(w5, b.w,  acc1);
        acc0 = fmaf(w6, cc.x, acc0);  acc1 = fmaf(w7, cc.y, acc1);
        acc0 = fmaf(w8, cc.z, acc0);  acc1 = fmaf(w9, cc.w, acc1);
        acc0 = fmaf(wA, dd.x, acc0);  acc1 = fmaf(wB, dd.y, acc1);
        acc0 = fmaf(wC, dd.z, acc0);  acc1 = fmaf(wD, dd.w, acc1);
        acc0 = fmaf(wE, e.x,  acc0);  acc1 = fmaf(wF, e.y,  acc1);
        out[(size_t)c * k_out + k] = acc0 + acc1;
    }

    // ---- cell_ids pass-through (second tuple element) ----
    out[(size_t)CCH * k_out + k] = (float)cell_ids[k];
}

extern "C" void kernel_launch(void* const* d_in, const int* in_sizes, int n_in_args,
                              void* d_out, int out_size)
{
    const float* x        = (const float*)d_in[0];   // (1, 8, N_IN) f32
    const int*   M_cols   = (const int*)  d_in[1];   // (K_OUT, 16) i32
    const float* M_vals   = (const float*)d_in[2];   // (K_OUT, 16) f32
    const int*   cell_ids = (const int*)  d_in[3];   // (K_OUT,)    i32

    const int N_IN  = in_sizes[0] / CCH;      // 3,145,728
    const int K_OUT = in_sizes[3];            // 786,432

    float* out = (float*)d_out;

    const int grid = (K_OUT + KPB - 1) / KPB; // 3072, exact
    sphere_down_kernel<<<grid, KPB>>>(x, M_cols, M_vals, cell_ids, out,
                                      N_IN, K_OUT);
}

// round 8
// speedup vs baseline: 7.3583x; 1.2069x over previous
#include <cuda_runtime.h>

// SphereDownGeo: y[c,k] = sum_d M_vals[k,d] * x[c, M_cols[k,d]]
// M_cols[k,d] = clip(4k + off, 0, N-1), off in [-6,10).
//
// Dense-window form: dense 16-weight vector w[j], j = col-(4k-6) in [0,16),
// built by an IN-REGISTER select network (scalar ternaries only -- no arrays,
// no if-arms, no SMEM scratch). Window read as 5x conflict-free LDS.128 per
// channel. Single barrier. Routing ALU work overlaps staging DRAM latency.

#define KPB    256
#define DEG    16
#define CCH    8
#define SEGV   260                 // float4s per channel window (1040 floats)

// Route one tap (index j, value v) into the 16 scalar weight registers.
// Ternary selects -> ISETP/FSEL/FADD, branch-free.
#define ROUTE(j, v)                                            \
    do { int _j = (j); float _v = (v);                         \
        w0 += (_j == 0 ) ? _v : 0.0f;                          \
        w1 += (_j == 1 ) ? _v : 0.0f;                          \
        w2 += (_j == 2 ) ? _v : 0.0f;                          \
        w3 += (_j == 3 ) ? _v : 0.0f;                          \
        w4 += (_j == 4 ) ? _v : 0.0f;                          \
        w5 += (_j == 5 ) ? _v : 0.0f;                          \
        w6 += (_j == 6 ) ? _v : 0.0f;                          \
        w7 += (_j == 7 ) ? _v : 0.0f;                          \
        w8 += (_j == 8 ) ? _v : 0.0f;                          \
        w9 += (_j == 9 ) ? _v : 0.0f;                          \
        wA += (_j == 10) ? _v : 0.0f;                          \
        wB += (_j == 11) ? _v : 0.0f;                          \
        wC += (_j == 12) ? _v : 0.0f;                          \
        wD += (_j == 13) ? _v : 0.0f;                          \
        wE += (_j == 14) ? _v : 0.0f;                          \
        wF += (_j == 15) ? _v : 0.0f;                          \
    } while (0)

__global__ __launch_bounds__(KPB)
void sphere_down_kernel(const float*  __restrict__ x,
                        const int*    __restrict__ M_cols,
                        const float*  __restrict__ M_vals,
                        const int*    __restrict__ cell_ids,
                        float*        __restrict__ out,
                        int n_in, int k_out)
{
    __shared__ __align__(16) float4 xs4[CCH * SEGV];

    const int k0 = blockIdx.x * KPB;
    const int t  = threadIdx.x;
    const int k  = k0 + t;

    const int vbase = k0 - 2;          // float4 window base: float idx 4*k0-8
    const int nv    = n_in >> 2;       // N_IN % 4 == 0

    // ---- Stage x window (LDG.128/STS.128, coalesced, zero-fill OOB).
    //      Issued first so DRAM latency overlaps the routing below. ----
    const float4* __restrict__ x4 = (const float4*)x;
    #pragma unroll 3
    for (int jj = t; jj < CCH * SEGV; jj += KPB) {
        int c = jj / SEGV;
        int i = jj - c * SEGV;
        int v = vbase + i;
        float4 val = make_float4(0.f, 0.f, 0.f, 0.f);
        if ((unsigned)v < (unsigned)nv)
            val = x4[(size_t)c * nv + v];
        xs4[c * SEGV + i] = val;
    }

    // ---- Load cols/vals (vectorized) and route into dense weights ----
    float w0 = 0.f, w1 = 0.f, w2 = 0.f, w3 = 0.f;
    float w4 = 0.f, w5 = 0.f, w6 = 0.f, w7 = 0.f;
    float w8 = 0.f, w9 = 0.f, wA = 0.f, wB = 0.f;
    float wC = 0.f, wD = 0.f, wE = 0.f, wF = 0.f;
    {
        const int4*   cp = (const int4*)(M_cols + (size_t)k * DEG);
        const float4* vp = (const float4*)(M_vals + (size_t)k * DEG);
        int4   c0 = cp[0], c1 = cp[1], c2 = cp[2], c3 = cp[3];
        float4 v0 = vp[0], v1 = vp[1], v2 = vp[2], v3 = vp[3];
        const int jref = 4 * k - 6;    // j = col - jref, provably in [0,16)
        ROUTE(c0.x - jref, v0.x);  ROUTE(c0.y - jref, v0.y);
        ROUTE(c0.z - jref, v0.z);  ROUTE(c0.w - jref, v0.w);
        ROUTE(c1.x - jref, v1.x);  ROUTE(c1.y - jref, v1.y);
        ROUTE(c1.z - jref, v1.z);  ROUTE(c1.w - jref, v1.w);
        ROUTE(c2.x - jref, v2.x);  ROUTE(c2.y - jref, v2.y);
        ROUTE(c2.z - jref, v2.z);  ROUTE(c2.w - jref, v2.w);
        ROUTE(c3.x - jref, v3.x);  ROUTE(c3.y - jref, v3.y);
        ROUTE(c3.z - jref, v3.z);  ROUTE(c3.w - jref, v3.w);
    }

    __syncthreads();

    // ---- Per channel: 5x conflict-free LDS.128 + 16 FMAs ----
    #pragma unroll
    for (int c = 0; c < CCH; c++) {
        const float4* base = xs4 + c * SEGV + t;
        float4 a  = base[0];
        float4 b  = base[1];
        float4 cc = base[2];
        float4 dd = base[3];
        float4 e  = base[4];
        // dense weight j multiplies window float 4t+2+j
        float acc0 = w0 * a.z;
        float acc1 = w1 * a.w;
        acc0 = fmaf(w2, b.x,  acc0);  acc1 = fmaf(w3, b.y,  acc1);
        acc0 = fmaf(w4, b.z,  acc0);  acc1 = fmaf(w5, b.w,  acc1);
        acc0 = fmaf(w6, cc.x, acc0);  acc1 = fmaf(w7, cc.y, acc1);
        acc0 = fmaf(w8, cc.z, acc0);  acc1 = fmaf(w9, cc.w, acc1);
        acc0 = fmaf(wA, dd.x, acc0);  acc1 = fmaf(wB, dd.y, acc1);
        acc0 = fmaf(wC, dd.z, acc0);  acc1 = fmaf(wD, dd.w, acc1);
        acc0 = fmaf(wE, e.x,  acc0);  acc1 = fmaf(wF, e.y,  acc1);
        out[(size_t)c * k_out + k] = acc0 + acc1;
    }

    // ---- cell_ids pass-through (second tuple element) ----
    out[(size_t)CCH * k_out + k] = (float)cell_ids[k];
}

extern "C" void kernel_launch(void* const* d_in, const int* in_sizes, int n_in_args,
                              void* d_out, int out_size)
{
    const float* x        = (const float*)d_in[0];   // (1, 8, N_IN) f32
    const int*   M_cols   = (const int*)  d_in[1];   // (K_OUT, 16) i32
    const float* M_vals   = (const float*)d_in[2];   // (K_OUT, 16) f32
    const int*   cell_ids = (const int*)  d_in[3];   // (K_OUT,)    i32

    const int N_IN  = in_sizes[0] / CCH;      // 3,145,728
    const int K_OUT = in_sizes[3];            // 786,432

    float* out = (float*)d_out;

    const int grid = (K_OUT + KPB - 1) / KPB; // 3072, exact
    sphere_down_kernel<<<grid, KPB>>>(x, M_cols, M_vals, cell_ids, out,
                                      N_IN, K_OUT);
}